// round 9
// baseline (speedup 1.0000x reference)
#include <cuda_runtime.h>
#include <cstdint>

// Problem constants (N=100000, E=3200000, D=165)
#define NMAX 100000
#define EMAX 3200000
#define D0 165
#define F1 32
#define F2 16
#define F3 2
#define CAP 128   // bucket capacity per dst; deg ~ Poisson(32), max@100k ~ 70

// Scratch (device globals — no allocation allowed). 16B-aligned for vector ops.
__device__ __align__(16) float g_buf0[NMAX * F1];   // hs1 (32 f/node, 128B rows)
__device__ __align__(16) float g_buf2[NMAX * F2];   // hs2 (16 f/node, 64B rows)
__device__ __align__(16) float g_buf1[NMAX * F3];   // hs3 (2 f/node, 8B rows)
__device__ __align__(16) int   g_cnt[NMAX];         // per-dst in-degree
__device__ __align__(16) int   g_bkt[(size_t)NMAX * CAP]; // src ids per dst

// ---------------------------------------------------------------------------
__global__ void k_zero_cnt(int n) {
    int i = blockIdx.x * blockDim.x + threadIdx.x;
    if (i < n) g_cnt[i] = 0;
}

// Single-pass bucket fill: hist + placement fused. edge_index is int32.
// 4 edges/thread, int4 vector loads (falls back to scalar on ragged tail).
__global__ void k_fill(const int* __restrict__ ei, int E, int N) {
    int i = blockIdx.x * blockDim.x + threadIdx.x;
    int e0 = i * 4;
    if (e0 >= E) return;
    if (((E & 3) == 0) && (e0 + 4 <= E)) {
        int4 s4 = __ldg((const int4*)ei + i);
        int4 d4 = __ldg((const int4*)(ei + E) + i);
        int ss[4] = {s4.x, s4.y, s4.z, s4.w};
        int dd[4] = {d4.x, d4.y, d4.z, d4.w};
#pragma unroll
        for (int j = 0; j < 4; j++) {
            int s = ss[j], d = dd[j];
            s = (s < 0) ? 0 : ((s >= N) ? N - 1 : s);
            d = (d < 0) ? 0 : ((d >= N) ? N - 1 : d);
            int pos = atomicAdd(&g_cnt[d], 1);
            if (pos < CAP) g_bkt[(size_t)d * CAP + pos] = s;
        }
    } else {
        for (int j = 0; j < 4; j++) {
            int e = e0 + j;
            if (e >= E) return;
            int s = ei[e];
            int d = ei[E + e];
            s = (s < 0) ? 0 : ((s >= N) ? N - 1 : s);
            d = (d < 0) ? 0 : ((d >= N) ? N - 1 : d);
            int pos = atomicAdd(&g_cnt[d], 1);
            if (pos < CAP) g_bkt[(size_t)d * CAP + pos] = s;
        }
    }
}

// ---------------------------------------------------------------------------
// GEMM1: hs1 = (x @ W1) * dinv. 4 rows per warp: one LDS feeds 4 FMAs.
__global__ void k_gemm1(const float* __restrict__ x,
                        const float* __restrict__ W1, int N) {
    __shared__ float sW[D0 * F1];
    for (int i = threadIdx.x; i < D0 * F1; i += blockDim.x) sW[i] = W1[i];
    __syncthreads();

    int warp = (blockIdx.x * blockDim.x + threadIdx.x) >> 5;
    int lane = threadIdx.x & 31;
    int r0 = warp * 4;
    if (r0 >= N) return;

    float xv[4][6];
#pragma unroll
    for (int r = 0; r < 4; r++) {
        int row = r0 + r;
        if (row >= N) row = N - 1;
        const float* xr = x + (size_t)row * D0;
#pragma unroll
        for (int j = 0; j < 6; j++) {
            int idx = j * 32 + lane;
            xv[r][j] = (idx < D0) ? __ldg(xr + idx) : 0.0f;
        }
    }

    float acc[4] = {0.f, 0.f, 0.f, 0.f};
#pragma unroll
    for (int j = 0; j < 6; j++) {
#pragma unroll
        for (int t = 0; t < 32; t++) {
            int k = j * 32 + t;
            if (k >= D0) break;
            float w = sW[k * F1 + lane];
#pragma unroll
            for (int r = 0; r < 4; r++) {
                float xk = __shfl_sync(0xffffffffu, xv[r][j], t);
                acc[r] = fmaf(xk, w, acc[r]);
            }
        }
    }
#pragma unroll
    for (int r = 0; r < 4; r++) {
        int row = r0 + r;
        if (row < N) {
            float dv = rsqrtf((float)g_cnt[row] + 1.0f);
            g_buf0[(size_t)row * F1 + lane] = acc[r] * dv;
        }
    }
}

// ---------------------------------------------------------------------------
// Fused agg1 + relu + gemm2: warp per dst.
// Gather: lane = (edge-slot = lane>>3, quad = lane&7); LDG.128 per lane covers
// 4 features of one edge; 4 edges in flight per step, 8 steps per 32-edge chunk.
__global__ void k_agg1g2(const float* __restrict__ W2,
                         const float* __restrict__ b1, int N) {
    __shared__ float sW[F1 * F2];
    __shared__ float sb[F1];
    for (int i = threadIdx.x; i < F1 * F2; i += blockDim.x) sW[i] = W2[i];
    if (threadIdx.x < F1) sb[threadIdx.x] = b1[threadIdx.x];
    __syncthreads();

    int d = (blockIdx.x * blockDim.x + threadIdx.x) >> 5;
    int lane = threadIdx.x & 31;
    if (d >= N) return;

    int eslot = lane >> 3;     // 0..3
    int q     = lane & 7;      // feature quad 0..7

    int cnt = g_cnt[d];
    float dv = rsqrtf((float)cnt + 1.0f);
    if (cnt > CAP) cnt = CAP;
    const int* row = g_bkt + (size_t)d * CAP;
    const float4* buf4 = (const float4*)g_buf0;   // 8 quads per node row

    float4 acc = make_float4(0.f, 0.f, 0.f, 0.f);
    int base = 0;
    while (base < cnt) {
        int m = min(32, cnt - base);
        int sid = (lane < m) ? __ldg(row + base + lane) : 0;
#pragma unroll
        for (int g = 0; g < 8; g++) {
            int t = g * 4 + eslot;
            int s = __shfl_sync(0xffffffffu, sid, t);
            if (t < m) {
                float4 v = __ldg(buf4 + (size_t)s * 8 + q);
                acc.x += v.x; acc.y += v.y; acc.z += v.z; acc.w += v.w;
            }
        }
        base += 32;
    }
    // combine the 4 edge-slots (butterfly over lane bits 3,4)
#pragma unroll
    for (int off = 8; off < 32; off <<= 1) {
        acc.x += __shfl_xor_sync(0xffffffffu, acc.x, off);
        acc.y += __shfl_xor_sync(0xffffffffu, acc.y, off);
        acc.z += __shfl_xor_sync(0xffffffffu, acc.z, off);
        acc.w += __shfl_xor_sync(0xffffffffu, acc.w, off);
    }
    // self term + bias + relu (per-quad, replicated across edge-slots)
    float4 self = __ldg(buf4 + (size_t)d * 8 + q);
    float4 bias = ((const float4*)sb)[q];
    float4 in4;
    in4.x = fmaxf(fmaf(acc.x + self.x, dv, bias.x), 0.0f);
    in4.y = fmaxf(fmaf(acc.y + self.y, dv, bias.y), 0.0f);
    in4.z = fmaxf(fmaf(acc.z + self.z, dv, bias.z), 0.0f);
    in4.w = fmaxf(fmaf(acc.w + self.w, dv, bias.w), 0.0f);

    // gemm2: lanes 0-15 handle quads 0-3 (k=0..15), lanes 16-31 quads 4-7
    int f = lane & 15;
    int jbase = (lane & 16) >> 2;   // 0 or 4
    float o = 0.0f;
#pragma unroll
    for (int jj = 0; jj < 4; jj++) {
        int j = jbase + jj;         // source quad; lives at lane j (replicated)
        float vx = __shfl_sync(0xffffffffu, in4.x, j);
        float vy = __shfl_sync(0xffffffffu, in4.y, j);
        float vz = __shfl_sync(0xffffffffu, in4.z, j);
        float vw = __shfl_sync(0xffffffffu, in4.w, j);
        o = fmaf(vx, sW[(4 * j + 0) * F2 + f], o);
        o = fmaf(vy, sW[(4 * j + 1) * F2 + f], o);
        o = fmaf(vz, sW[(4 * j + 2) * F2 + f], o);
        o = fmaf(vw, sW[(4 * j + 3) * F2 + f], o);
    }
    o += __shfl_xor_sync(0xffffffffu, o, 16);
    if (lane < 16) g_buf2[(size_t)d * F2 + f] = o * dv;
}

// ---------------------------------------------------------------------------
// Fused agg2 + relu + gemm3: 16-lane group per dst (2 dsts/warp).
// Within a group: eslot = (lane&15)>>2 (4 edges in flight), quad = lane&3.
__global__ void k_agg2g3(const float* __restrict__ W3,
                         const float* __restrict__ b2, int N) {
    __shared__ float sW[F2 * F3];
    __shared__ float sb[F2];
    if (threadIdx.x < F2 * F3) sW[threadIdx.x] = W3[threadIdx.x];
    if (threadIdx.x < F2) sb[threadIdx.x] = b2[threadIdx.x];
    __syncthreads();

    int d = (blockIdx.x * blockDim.x + threadIdx.x) >> 4;
    int l16 = threadIdx.x & 15;
    unsigned hmask = 0xFFFFu << (threadIdx.x & 16);
    if (d >= N) return;

    int eslot = l16 >> 2;   // 0..3
    int q     = l16 & 3;    // quad 0..3

    int cnt = g_cnt[d];
    float dv = rsqrtf((float)cnt + 1.0f);
    if (cnt > CAP) cnt = CAP;
    const int* row = g_bkt + (size_t)d * CAP;
    const float4* buf4 = (const float4*)g_buf2;   // 4 quads per node row

    float4 acc = make_float4(0.f, 0.f, 0.f, 0.f);
    int base = 0;
    while (base < cnt) {
        int m = min(16, cnt - base);
        int sid = (l16 < m) ? __ldg(row + base + l16) : 0;
#pragma unroll
        for (int g = 0; g < 4; g++) {
            int t = g * 4 + eslot;
            int s = __shfl_sync(hmask, sid, t, 16);
            if (t < m) {
                float4 v = __ldg(buf4 + (size_t)s * 4 + q);
                acc.x += v.x; acc.y += v.y; acc.z += v.z; acc.w += v.w;
            }
        }
        base += 16;
    }
    // combine edge-slots (lane bits 2,3 within the 16-group)
#pragma unroll
    for (int off = 4; off < 16; off <<= 1) {
        acc.x += __shfl_xor_sync(hmask, acc.x, off, 16);
        acc.y += __shfl_xor_sync(hmask, acc.y, off, 16);
        acc.z += __shfl_xor_sync(hmask, acc.z, off, 16);
        acc.w += __shfl_xor_sync(hmask, acc.w, off, 16);
    }
    float4 self = __ldg(buf4 + (size_t)d * 4 + q);
    float4 bias = ((const float4*)sb)[q];
    float4 in4;
    in4.x = fmaxf(fmaf(acc.x + self.x, dv, bias.x), 0.0f);
    in4.y = fmaxf(fmaf(acc.y + self.y, dv, bias.y), 0.0f);
    in4.z = fmaxf(fmaf(acc.z + self.z, dv, bias.z), 0.0f);
    in4.w = fmaxf(fmaf(acc.w + self.w, dv, bias.w), 0.0f);

    // gemm3: per-quad partial dot with both output columns, then reduce over q
    float p0, p1;
    p0 = in4.x * sW[(4 * q + 0) * F3 + 0];
    p1 = in4.x * sW[(4 * q + 0) * F3 + 1];
    p0 = fmaf(in4.y, sW[(4 * q + 1) * F3 + 0], p0);
    p1 = fmaf(in4.y, sW[(4 * q + 1) * F3 + 1], p1);
    p0 = fmaf(in4.z, sW[(4 * q + 2) * F3 + 0], p0);
    p1 = fmaf(in4.z, sW[(4 * q + 2) * F3 + 1], p1);
    p0 = fmaf(in4.w, sW[(4 * q + 3) * F3 + 0], p0);
    p1 = fmaf(in4.w, sW[(4 * q + 3) * F3 + 1], p1);
#pragma unroll
    for (int off = 1; off < 4; off <<= 1) {
        p0 += __shfl_xor_sync(hmask, p0, off, 16);
        p1 += __shfl_xor_sync(hmask, p1, off, 16);
    }
    if (l16 == 0) {
        float2* hp = (float2*)(g_buf1 + (size_t)d * F3);
        *hp = make_float2(p0 * dv, p1 * dv);
    }
}

// ---------------------------------------------------------------------------
// Aggregation layer 3 + bias + log_softmax. Warp per dst; lane = edge,
// float2 load per lane (no shuffles in the gather loop).
__global__ void k_agg3(const float* __restrict__ b3,
                       float* __restrict__ out, int N) {
    int d = (blockIdx.x * blockDim.x + threadIdx.x) >> 5;
    int lane = threadIdx.x & 31;
    if (d >= N) return;
    int cnt = g_cnt[d];
    float dv = rsqrtf((float)cnt + 1.0f);
    if (cnt > CAP) cnt = CAP;
    const int* row = g_bkt + (size_t)d * CAP;
    const float2* buf2 = (const float2*)g_buf1;

    float ax = 0.0f, ay = 0.0f;
    for (int base = 0; base < cnt; base += 32) {
        int t = base + lane;
        if (t < cnt) {
            int s = __ldg(row + t);
            float2 v = __ldg(buf2 + s);
            ax += v.x; ay += v.y;
        }
    }
#pragma unroll
    for (int off = 16; off; off >>= 1) {
        ax += __shfl_xor_sync(0xffffffffu, ax, off);
        ay += __shfl_xor_sync(0xffffffffu, ay, off);
    }
    if (lane == 0) {
        float2 self = __ldg(buf2 + d);
        float a0 = fmaf(ax + self.x, dv, __ldg(b3 + 0));
        float a1 = fmaf(ay + self.y, dv, __ldg(b3 + 1));
        float m = fmaxf(a0, a1);
        float l = m + logf(expf(a0 - m) + expf(a1 - m));
        float2* op = (float2*)(out + (size_t)d * 2);
        *op = make_float2(a0 - l, a1 - l);
    }
}

// ---------------------------------------------------------------------------
extern "C" void kernel_launch(void* const* d_in, const int* in_sizes, int n_in,
                              void* d_out, int out_size) {
    const float* x  = (const float*)d_in[0];
    const int*   ei = (const int*)d_in[1];
    const float* W1 = (const float*)d_in[2];
    const float* b1 = (const float*)d_in[3];
    const float* W2 = (const float*)d_in[4];
    const float* b2 = (const float*)d_in[5];
    const float* W3 = (const float*)d_in[6];
    const float* b3 = (const float*)d_in[7];
    float* out      = (float*)d_out;

    int N = in_sizes[0] / D0;
    int E = in_sizes[1] / 2;
    if (N > NMAX) N = NMAX;
    if (E > EMAX) E = EMAX;

    int nb_n = (N + 255) / 256;

    // Bucket-CSR build (one edge-list pass)
    k_zero_cnt<<<nb_n, 256>>>(N);
    k_fill<<<(E / 4 + 255) / 256, 256>>>(ei, E, N);

    // Layer 1 GEMM, then fused layers
    k_gemm1<<<(((N + 3) / 4) * 32 + 255) / 256, 256>>>(x, W1, N);
    k_agg1g2<<<(N * 32 + 255) / 256, 256>>>(W2, b1, N);
    k_agg2g3<<<(N * 16 + 255) / 256, 256>>>(W3, b2, N);
    k_agg3<<<(N * 32 + 255) / 256, 256>>>(b3, out, N);
}